// round 2
// baseline (speedup 1.0000x reference)
#include <cuda_runtime.h>
#include <float.h>

#define POOLW 7
#define IMG_W 2048
#define IMG_HW (2048 * 2048)
#define NBOX_THREADS 128
#define MAX_SMEM_BYTES (2 * 96 * 96 * 4)

__global__ __launch_bounds__(NBOX_THREADS)
void roi_pool_fc_kernel(const float* __restrict__ feature,
                        const float* __restrict__ boxes,
                        const int*   __restrict__ coords,
                        const float* __restrict__ fc_w,
                        const float* __restrict__ fc_b,
                        float* __restrict__ out) {
    extern __shared__ float crop[];           // [2][h][w] compact
    __shared__ float pooled[98];
    __shared__ float delta[4];

    const int b   = blockIdx.x;
    const int tid = threadIdx.x;

    const int y1 = coords[b * 4 + 0];
    const int x1 = coords[b * 4 + 1];
    const int y2 = coords[b * 4 + 2];
    const int x2 = coords[b * 4 + 3];
    const int h  = y2 - y1;
    const int w  = x2 - x1;
    const int hw = h * w;

    // ---- Stage crop into shared memory (coalesced within rows) ----
    for (int idx = tid; idx < 2 * hw; idx += NBOX_THREADS) {
        int c   = idx / hw;
        int rem = idx - c * hw;
        int r   = rem / w;
        int cc  = rem - r * w;
        crop[idx] = feature[c * IMG_HW + (y1 + r) * IMG_W + (x1 + cc)];
    }
    __syncthreads();

    // ---- Adaptive max pool: thread t -> (c, i, j), channel-major flatten ----
    if (tid < 98) {
        int c   = tid / 49;
        int rem = tid - c * 49;
        int i   = rem / 7;
        int j   = rem - i * 7;

        int sr = (i * h) / POOLW;
        int er = ((i + 1) * h + POOLW - 1) / POOLW;
        int sc = (j * w) / POOLW;
        int ec = ((j + 1) * w + POOLW - 1) / POOLW;

        const float* base = crop + c * hw;
        float m = -FLT_MAX;
        for (int r = sr; r < er; ++r) {
            const float* row = base + r * w;
            for (int x = sc; x < ec; ++x)
                m = fmaxf(m, row[x]);
        }
        pooled[tid] = m;
    }
    __syncthreads();

    // ---- FC(98 -> 4) + ReLU ----
    if (tid < 4) {
        float acc = fc_b[tid];
        const float* wrow = fc_w + tid * 98;
        #pragma unroll
        for (int k = 0; k < 98; ++k)
            acc = fmaf(wrow[k], pooled[k], acc);
        delta[tid] = fmaxf(acc, 0.0f);
    }
    __syncthreads();

    // ---- Write output row: boxes copy, cols 2..5 += delta ----
    if (tid < 6) {
        float v = boxes[b * 6 + tid];
        if (tid >= 2) v += delta[tid - 2];
        out[b * 6 + tid] = v;
    }
}

extern "C" void kernel_launch(void* const* d_in, const int* in_sizes, int n_in,
                              void* d_out, int out_size) {
    const float* feature = (const float*)d_in[0];
    const float* boxes   = (const float*)d_in[1];
    const int*   coords  = (const int*)d_in[2];
    const float* fc_w    = (const float*)d_in[3];
    const float* fc_b    = (const float*)d_in[4];
    float* out = (float*)d_out;

    const int nbox = in_sizes[2] / 4;   // box_coords has 4 ints per box

    cudaFuncSetAttribute(roi_pool_fc_kernel,
                         cudaFuncAttributeMaxDynamicSharedMemorySize,
                         MAX_SMEM_BYTES);

    roi_pool_fc_kernel<<<nbox, NBOX_THREADS, MAX_SMEM_BYTES>>>(
        feature, boxes, coords, fc_w, fc_b, out);
}

// round 7
// speedup vs baseline: 3.3309x; 3.3309x over previous
#include <cuda_runtime.h>
#include <float.h>

#define POOLW 7
#define IMG_W 2048
#define IMG_HW (2048 * 2048)
#define NTHREADS 128
#define MAXW 96

__global__ __launch_bounds__(NTHREADS)
void roi_pool_fc_kernel(const float* __restrict__ feature,
                        const float* __restrict__ boxes,
                        const int*   __restrict__ coords,
                        const float* __restrict__ fc_w,
                        const float* __restrict__ fc_b,
                        float* __restrict__ out) {
    // rowp[i*2+c][col] : row-pooled maxes, 14*96 floats = 5376 B
    __shared__ float rowp[14 * MAXW];
    __shared__ float pooled[98];
    __shared__ float delta[4];

    const int b   = blockIdx.x;
    const int tid = threadIdx.x;

    const int y1 = __ldg(&coords[b * 4 + 0]);
    const int x1 = __ldg(&coords[b * 4 + 1]);
    const int h  = __ldg(&coords[b * 4 + 2]) - y1;
    const int w  = __ldg(&coords[b * 4 + 3]) - x1;

    // ---- Stage 1: row-wise max per (output-row i, channel c, col-pair) ----
    // Each thread owns two adjacent columns: 2 independent loads per row step
    // (MLP=2), warp spans 64 contiguous columns -> full sector utilization.
    const int pairs  = (w + 1) >> 1;
    const int total1 = 14 * pairs;       // 7 output rows x 2 channels x pairs
    for (int idx = tid; idx < total1; idx += NTHREADS) {
        const int ic   = idx / pairs;    // ic = i*2 + c
        const int q    = idx - ic * pairs;
        const int col0 = q * 2;
        const int i    = ic >> 1;
        const int c    = ic & 1;
        const bool has1 = (col0 + 1) < w;

        const int sr = (i * h) / POOLW;
        const int er = ((i + 1) * h + POOLW - 1) / POOLW;

        const float* p = feature + c * IMG_HW + (y1 + sr) * IMG_W + (x1 + col0);
        float m0 = -FLT_MAX, m1 = -FLT_MAX;
        for (int r = sr; r < er; ++r) {
            const float v0 = p[0];
            const float v1 = p[1];        // x1+col0+1 <= x1+w <= 2047: in-bounds
            m0 = fmaxf(m0, v0);
            m1 = fmaxf(m1, v1);
            p += IMG_W;
        }
        rowp[ic * MAXW + col0] = m0;
        if (has1) rowp[ic * MAXW + col0 + 1] = m1;
    }
    __syncthreads();

    // ---- Stage 2: col-wise max over rowp -> pooled[c*49 + i*7 + j] ----
    if (tid < 98) {
        const int c   = tid / 49;
        const int rem = tid - c * 49;
        const int i   = rem / 7;
        const int j   = rem - i * 7;

        const int sc = (j * w) / POOLW;
        const int ec = ((j + 1) * w + POOLW - 1) / POOLW;

        const float* base = rowp + (i * 2 + c) * MAXW;
        float m = -FLT_MAX;
        for (int x = sc; x < ec; ++x)
            m = fmaxf(m, base[x]);
        pooled[tid] = m;
    }
    __syncthreads();

    // ---- FC(98 -> 4) + ReLU : warp o computes output o ----
    const int warp = tid >> 5;
    const int lane = tid & 31;
    {
        float acc = 0.0f;
        const float* wrow = fc_w + warp * 98;
        for (int k = lane; k < 98; k += 32)
            acc = fmaf(wrow[k], pooled[k], acc);
        #pragma unroll
        for (int off = 16; off > 0; off >>= 1)
            acc += __shfl_down_sync(0xFFFFFFFFu, acc, off);
        if (lane == 0)
            delta[warp] = fmaxf(acc + fc_b[warp], 0.0f);
    }
    __syncthreads();

    // ---- Output row: boxes copy, cols 2..5 += delta ----
    if (tid < 6) {
        float v = boxes[b * 6 + tid];
        if (tid >= 2) v += delta[tid - 2];
        out[b * 6 + tid] = v;
    }
}

extern "C" void kernel_launch(void* const* d_in, const int* in_sizes, int n_in,
                              void* d_out, int out_size) {
    const float* feature = (const float*)d_in[0];
    const float* boxes   = (const float*)d_in[1];
    const int*   coords  = (const int*)d_in[2];
    const float* fc_w    = (const float*)d_in[3];
    const float* fc_b    = (const float*)d_in[4];
    float* out = (float*)d_out;

    const int nbox = in_sizes[2] / 4;

    roi_pool_fc_kernel<<<nbox, NTHREADS>>>(feature, boxes, coords, fc_w, fc_b, out);
}

// round 10
// speedup vs baseline: 3.4060x; 1.0226x over previous
#include <cuda_runtime.h>
#include <float.h>

#define POOLW 7
#define IMG_W 2048
#define IMG_HW (2048 * 2048)
#define NTHREADS 448          // 14 warps: one per (output-row i, channel c)
#define MAXW 96

__global__ __launch_bounds__(NTHREADS)
void roi_pool_fc_kernel(const float* __restrict__ feature,
                        const float* __restrict__ boxes,
                        const int*   __restrict__ coords,
                        const float* __restrict__ fc_w,
                        const float* __restrict__ fc_b,
                        float* __restrict__ out) {
    // rowp[ic][col] : row-pooled maxes, 14*96 floats = 5376 B
    __shared__ float rowp[14 * MAXW];
    __shared__ float pooled[98];
    __shared__ float delta[4];

    const int b    = blockIdx.x;
    const int tid  = threadIdx.x;
    const int warp = tid >> 5;        // 0..13  == ic = i*2 + c
    const int lane = tid & 31;

    const int y1 = __ldg(&coords[b * 4 + 0]);
    const int x1 = __ldg(&coords[b * 4 + 1]);
    const int h  = __ldg(&coords[b * 4 + 2]) - y1;
    const int w  = __ldg(&coords[b * 4 + 3]) - x1;

    // ---- Stage 1: warp `ic` computes row-max slice rowp[ic][0..w) ----
    // Lane covers columns lane, lane+32, lane+64: three independent chains,
    // fully coalesced row loads, <=14 row iterations. Predicated loads keep
    // the warp convergent and avoid reading beyond the box.
    {
        const int i  = warp >> 1;
        const int c  = warp & 1;
        const int sr = (i * h) / POOLW;
        const int er = ((i + 1) * h + POOLW - 1) / POOLW;

        const int c0 = lane, c1 = lane + 32, c2 = lane + 64;
        const bool has0 = c0 < w, has1 = c1 < w, has2 = c2 < w;

        const float* p = feature + c * IMG_HW + (y1 + sr) * IMG_W + x1;
        float m0 = -FLT_MAX, m1 = -FLT_MAX, m2 = -FLT_MAX;
        #pragma unroll 2
        for (int r = sr; r < er; ++r) {
            if (has0) m0 = fmaxf(m0, p[c0]);
            if (has1) m1 = fmaxf(m1, p[c1]);
            if (has2) m2 = fmaxf(m2, p[c2]);
            p += IMG_W;
        }
        float* dst = rowp + warp * MAXW;
        if (has0) dst[c0] = m0;
        if (has1) dst[c1] = m1;
        if (has2) dst[c2] = m2;
    }
    __syncthreads();

    // ---- Stage 2: col-wise max over rowp -> pooled[c*49 + i*7 + j] ----
    if (tid < 98) {
        const int c   = tid / 49;
        const int rem = tid - c * 49;
        const int i   = rem / 7;
        const int j   = rem - i * 7;

        const int sc = (j * w) / POOLW;
        const int ec = ((j + 1) * w + POOLW - 1) / POOLW;

        const float* base = rowp + (i * 2 + c) * MAXW;
        float m = -FLT_MAX;
        for (int x = sc; x < ec; ++x)
            m = fmaxf(m, base[x]);
        pooled[tid] = m;
    }
    __syncthreads();

    // ---- FC(98 -> 4) + ReLU : warp o (0..3) computes output o ----
    if (warp < 4) {
        float acc = 0.0f;
        const float* wrow = fc_w + warp * 98;
        for (int k = lane; k < 98; k += 32)
            acc = fmaf(wrow[k], pooled[k], acc);
        #pragma unroll
        for (int off = 16; off > 0; off >>= 1)
            acc += __shfl_down_sync(0xFFFFFFFFu, acc, off);
        if (lane == 0)
            delta[warp] = fmaxf(acc + fc_b[warp], 0.0f);
    }
    __syncthreads();

    // ---- Output row: boxes copy, cols 2..5 += delta ----
    if (tid < 6) {
        float v = boxes[b * 6 + tid];
        if (tid >= 2) v += delta[tid - 2];
        out[b * 6 + tid] = v;
    }
}

extern "C" void kernel_launch(void* const* d_in, const int* in_sizes, int n_in,
                              void* d_out, int out_size) {
    const float* feature = (const float*)d_in[0];
    const float* boxes   = (const float*)d_in[1];
    const int*   coords  = (const int*)d_in[2];
    const float* fc_w    = (const float*)d_in[3];
    const float* fc_b    = (const float*)d_in[4];
    float* out = (float*)d_out;

    const int nbox = in_sizes[2] / 4;

    roi_pool_fc_kernel<<<nbox, NTHREADS>>>(feature, boxes, coords, fc_w, fc_b, out);
}

// round 11
// speedup vs baseline: 4.0567x; 1.1910x over previous
#include <cuda_runtime.h>
#include <float.h>

#define POOLW 7
#define IMG_W 2048
#define IMG_HW (2048 * 2048)
#define NTHREADS 224          // 7 warps; warp w owns slices ic = w and ic = w+7
#define MAXW 96
#define MAXROWS 14            // max bin height for h <= 95

__global__ __launch_bounds__(NTHREADS)
void roi_pool_fc_kernel(const float* __restrict__ feature,
                        const float* __restrict__ boxes,
                        const int*   __restrict__ coords,
                        const float* __restrict__ fc_w,
                        const float* __restrict__ fc_b,
                        float* __restrict__ out) {
    __shared__ float rowp[14 * MAXW];   // [ic][col] row-pooled maxes, 5376 B
    __shared__ float pooled[98];
    __shared__ float delta[4];

    const int b    = blockIdx.x;
    const int tid  = threadIdx.x;
    const int warp = tid >> 5;          // 0..6
    const int lane = tid & 31;

    const int y1 = __ldg(&coords[b * 4 + 0]);
    const int x1 = __ldg(&coords[b * 4 + 1]);
    const int h  = __ldg(&coords[b * 4 + 2]) - y1;
    const int w  = __ldg(&coords[b * 4 + 3]) - x1;

    // ---- Stage 1: each warp computes TWO row-max slices (ic and ic+7) ----
    // Fixed 14-trip fully-unrolled row loop with predication: every LDG in
    // stage 1 is independent -> one memory round trip instead of ~n/2.
    {
        const int c0 = lane, c1 = lane + 32, c2 = lane + 64;
        const bool has0 = c0 < w, has1 = c1 < w, has2 = c2 < w;

        const int icA = warp,  icB = warp + 7;
        const int iA = icA >> 1, cA = icA & 1;
        const int iB = icB >> 1, cB = icB & 1;

        const int srA = (iA * h) / POOLW;
        const int nA  = ((iA + 1) * h + POOLW - 1) / POOLW - srA;
        const int srB = (iB * h) / POOLW;
        const int nB  = ((iB + 1) * h + POOLW - 1) / POOLW - srB;

        const float* pA = feature + cA * IMG_HW + (y1 + srA) * IMG_W + x1;
        const float* pB = feature + cB * IMG_HW + (y1 + srB) * IMG_W + x1;

        float a0 = -FLT_MAX, a1 = -FLT_MAX, a2 = -FLT_MAX;
        float b0 = -FLT_MAX, b1 = -FLT_MAX, b2 = -FLT_MAX;

        #pragma unroll
        for (int k = 0; k < MAXROWS; ++k) {
            const bool inA = k < nA;
            const bool inB = k < nB;
            if (inA && has0) a0 = fmaxf(a0, pA[k * IMG_W + c0]);
            if (inA && has1) a1 = fmaxf(a1, pA[k * IMG_W + c1]);
            if (inA && has2) a2 = fmaxf(a2, pA[k * IMG_W + c2]);
            if (inB && has0) b0 = fmaxf(b0, pB[k * IMG_W + c0]);
            if (inB && has1) b1 = fmaxf(b1, pB[k * IMG_W + c1]);
            if (inB && has2) b2 = fmaxf(b2, pB[k * IMG_W + c2]);
        }

        float* dA = rowp + icA * MAXW;
        float* dB = rowp + icB * MAXW;
        if (has0) { dA[c0] = a0; dB[c0] = b0; }
        if (has1) { dA[c1] = a1; dB[c1] = b1; }
        if (has2) { dA[c2] = a2; dB[c2] = b2; }
    }
    __syncthreads();

    // ---- Stage 2: col-wise max over rowp -> pooled[c*49 + i*7 + j] ----
    if (tid < 98) {
        const int c   = tid / 49;
        const int rem = tid - c * 49;
        const int i   = rem / 7;
        const int j   = rem - i * 7;

        const int sc = (j * w) / POOLW;
        const int ec = ((j + 1) * w + POOLW - 1) / POOLW;

        const float* base = rowp + (i * 2 + c) * MAXW;
        float m = -FLT_MAX;
        for (int x = sc; x < ec; ++x)
            m = fmaxf(m, base[x]);
        pooled[tid] = m;
    }
    __syncthreads();

    // ---- FC(98 -> 4) + ReLU : warp o (0..3) computes output o ----
    if (warp < 4) {
        float acc = 0.0f;
        const float* wrow = fc_w + warp * 98;
        for (int k = lane; k < 98; k += 32)
            acc = fmaf(wrow[k], pooled[k], acc);
        #pragma unroll
        for (int off = 16; off > 0; off >>= 1)
            acc += __shfl_down_sync(0xFFFFFFFFu, acc, off);
        if (lane == 0)
            delta[warp] = fmaxf(acc + fc_b[warp], 0.0f);
    }
    __syncthreads();

    // ---- Output row: boxes copy, cols 2..5 += delta ----
    if (tid < 6) {
        float v = boxes[b * 6 + tid];
        if (tid >= 2) v += delta[tid - 2];
        out[b * 6 + tid] = v;
    }
}

extern "C" void kernel_launch(void* const* d_in, const int* in_sizes, int n_in,
                              void* d_out, int out_size) {
    const float* feature = (const float*)d_in[0];
    const float* boxes   = (const float*)d_in[1];
    const int*   coords  = (const int*)d_in[2];
    const float* fc_w    = (const float*)d_in[3];
    const float* fc_b    = (const float*)d_in[4];
    float* out = (float*)d_out;

    const int nbox = in_sizes[2] / 4;

    roi_pool_fc_kernel<<<nbox, NTHREADS>>>(feature, boxes, coords, fc_w, fc_b, out);
}